// round 11
// baseline (speedup 1.0000x reference)
#include <cuda_runtime.h>
#include <cstdint>

// SSIM over 11x11 patches — persistent blocks + 6-slot cp.async ring.
// img_pred: [4, 2048, 16, 121, 3] f32   (~190 MB)
// img_gt:   [2048, 16, 121, 3] f32      (~47.6 MB)
// out:      [4, 2048, 16] f32
//
// R10's DRAM idle (~27%) was wave-synchronized stage/compute alternation.
// R11: persistent-ish blocks (grid=888=148SMx6) each own ~9-10 tiles
// (tile = 4 rows). Streams (gt, v0..v3 per tile) flow through a 6-slot
// ring: at phase k of tile t we issue the kind-k stream of tile t+GRID
// into the slot freed last phase, commit exactly one group per phase
// (empty commits in the tail), wait_group 5, consume. Every block keeps
// ~5 streams (~29KB) in flight while computing -> DRAM fed continuously.
// Compute = R10: register-cached gt, f32x2 packed stats, fold+butterfly.

#define NN       2048
#define NP       16
#define ROW      363                       // 121 patches * 3 channels
#define VSTRIDE  ((size_t)NN * NP * ROW)   // floats per view
#define NT       ((NN * NP) / 4)           // 8192 tiles (4 rows each)
#define TILEF    (4 * ROW)                 // 1452 floats per stream
#define TILE4    (TILEF / 4)               // 363 float4
#define SLOTF    1488                      // slot floats (zero-padded tail)
#define NSLOT    6
#define GRID     888                       // 148 SMs x 6 blocks

using ull = unsigned long long;

__device__ __forceinline__ void cp16(uint32_t dst, const void* src) {
    asm volatile("cp.async.cg.shared.global [%0], [%1], 16;" :: "r"(dst), "l"(src));
}
__device__ __forceinline__ ull pk2(float lo, float hi) {
    ull r; asm("mov.b64 %0, {%1, %2};" : "=l"(r) : "f"(lo), "f"(hi)); return r;
}
__device__ __forceinline__ void up2(ull v, float& lo, float& hi) {
    asm("mov.b64 {%0, %1}, %2;" : "=f"(lo), "=f"(hi) : "l"(v));
}
__device__ __forceinline__ ull fma2_(ull a, ull b, ull c) {
    ull d; asm("fma.rn.f32x2 %0, %1, %2, %3;" : "=l"(d) : "l"(a), "l"(b), "l"(c)); return d;
}
__device__ __forceinline__ ull mul2_(ull a, ull b) {
    ull d; asm("mul.rn.f32x2 %0, %1, %2;" : "=l"(d) : "l"(a), "l"(b)); return d;
}
__device__ __forceinline__ ull add2_(ull a, ull b) {
    ull d; asm("add.rn.f32x2 %0, %1, %2;" : "=l"(d) : "l"(a), "l"(b)); return d;
}

__global__ __launch_bounds__(128) void ssim_kernel(
    const float* __restrict__ pred,
    const float* __restrict__ gt,
    float* __restrict__ out)
{
    __shared__ float ring[NSLOT][SLOTF];
    __shared__ float sg6[6];
    __shared__ float sW[128];

    const int tid  = threadIdx.x;
    const int wid  = tid >> 5;
    const int lane = tid & 31;
    const int t0   = blockIdx.x;

    #define STAGE(srcptr, slot) do {                                        \
        const float4* __restrict__ s4_ = (const float4*)(srcptr);           \
        uint32_t d_ = (uint32_t)__cvta_generic_to_shared(&ring[(slot)][0]); \
        for (int i_ = tid; i_ < TILE4; i_ += 128)                           \
            cp16(d_ + i_ * 16, s4_ + i_);                                   \
    } while (0)

    // ---- prologue: issue tile t0's 5 streams (slots 0..4), 5 groups ----
    STAGE(gt + (size_t)t0 * TILEF, 0);
    asm volatile("cp.async.commit_group;");
    #pragma unroll
    for (int v = 0; v < 4; v++) {
        STAGE(pred + v * VSTRIDE + (size_t)t0 * TILEF, v + 1);
        asm volatile("cp.async.commit_group;");
    }

    // ---- while loads fly: zero slot pads, build weight table ----
    #pragma unroll
    for (int s = 0; s < NSLOT; s++)
        for (int i = TILEF + tid; i < SLOTF; i += 128) ring[s][i] = 0.f;
    if (tid < 6) {
        float d = (float)tid;
        sg6[tid] = expf(-d * d * (1.0f / 4.5f));   // sigma = 1.5
    }
    __syncthreads();
    {
        float S = sg6[0] + 2.0f * (sg6[1] + sg6[2] + sg6[3] + sg6[4] + sg6[5]);
        float invS2 = 1.0f / (S * S);
        if (tid < 121) {
            int py = tid / 11, px = tid % 11;
            int dy = py - 5; if (dy < 0) dy = -dy;
            int dx = px - 5; if (dx < 0) dx = -dx;
            sW[tid] = sg6[dy] * sg6[dx] * invS2;
        } else if (tid < 128) {
            sW[tid] = 0.f;                          // tail patches contribute 0
        }
    }
    __syncthreads();

    float wk[4];  ull wkp[4];
    #pragma unroll
    for (int k = 0; k < 4; k++) {
        wk[k]  = sW[k * 32 + lane];
        wkp[k] = pk2(wk[k], wk[k]);
    }

    const int wbase = wid * ROW;
    int cur = 0;                     // slot of the stream being consumed

    for (int t = t0; t < NT; t += GRID) {
        const int  tn      = t + GRID;
        const bool hasnext = (tn < NT);

        // Accumulators: channels (0,1) packed, channel 2 scalar.
        ull  m1p[4], q2p[4], pgp[4];
        float m1s[4], q2s[4], pgs[4];
        ull  m2p = 0, g2p = 0;
        float m2s = 0.f, g2s = 0.f;
        #pragma unroll
        for (int v = 0; v < 4; v++) {
            m1p[v] = 0; q2p[v] = 0; pgp[v] = 0;
            m1s[v] = 0.f; q2s[v] = 0.f; pgs[v] = 0.f;
        }
        ull  bcp[4];    // cached gt (ch0,ch1) per k
        float bcs[4];   // cached gt ch2 per k

        // ---- phase 0: gt ----
        {
            const int isl = (cur == 0) ? NSLOT - 1 : cur - 1;
            if (hasnext) STAGE(gt + (size_t)tn * TILEF, isl);
            asm volatile("cp.async.commit_group;");
            asm volatile("cp.async.wait_group 5;");
            __syncthreads();
            const float* __restrict__ B = &ring[cur][wbase];
            #pragma unroll
            for (int k = 0; k < 4; k++) {
                const int base = 3 * (k * 32 + lane);
                const float b0 = B[base + 0];
                const float b1 = B[base + 1];
                const float b2 = B[base + 2];
                const ull bp = pk2(b0, b1);
                bcp[k] = bp;  bcs[k] = b2;
                const ull wbp = mul2_(wkp[k], bp);
                m2p = add2_(m2p, wbp);
                g2p = fma2_(wbp, bp, g2p);
                const float wb2 = wk[k] * b2;
                m2s += wb2;
                g2s = fmaf(wb2, b2, g2s);
            }
            __syncthreads();
            cur = (cur == NSLOT - 1) ? 0 : cur + 1;
        }

        // ---- phases 1..4: views ----
        #pragma unroll
        for (int v = 0; v < 4; v++) {
            const int isl = (cur == 0) ? NSLOT - 1 : cur - 1;
            if (hasnext) STAGE(pred + v * VSTRIDE + (size_t)tn * TILEF, isl);
            asm volatile("cp.async.commit_group;");
            asm volatile("cp.async.wait_group 5;");
            __syncthreads();
            const float* __restrict__ A = &ring[cur][wbase];
            #pragma unroll
            for (int k = 0; k < 4; k++) {
                const int base = 3 * (k * 32 + lane);
                const float a0 = A[base + 0];
                const float a1 = A[base + 1];
                const float a2 = A[base + 2];
                const ull ap = pk2(a0, a1);
                const ull wa = mul2_(wkp[k], ap);
                m1p[v] = add2_(m1p[v], wa);
                q2p[v] = fma2_(wa, ap, q2p[v]);
                pgp[v] = fma2_(wa, bcp[k], pgp[v]);
                const float wa2 = wk[k] * a2;
                m1s[v] += wa2;
                q2s[v] = fmaf(wa2, a2, q2s[v]);
                pgs[v] = fmaf(wa2, bcs[k], pgs[v]);
            }
            __syncthreads();
            cur = (cur == NSLOT - 1) ? 0 : cur + 1;
        }

        // ---- reduction + epilogue (registers only; overlaps next prefetch) ----
        float M1[4][3], Q2[4][3], PG[4][3], M2[3], G2[3];
        #pragma unroll
        for (int v = 0; v < 4; v++) {
            up2(m1p[v], M1[v][0], M1[v][1]);  M1[v][2] = m1s[v];
            up2(q2p[v], Q2[v][0], Q2[v][1]);  Q2[v][2] = q2s[v];
            up2(pgp[v], PG[v][0], PG[v][1]);  PG[v][2] = pgs[v];
        }
        up2(m2p, M2[0], M2[1]);  M2[2] = m2s;
        up2(g2p, G2[0], G2[1]);  G2[2] = g2s;

        const bool hi = (lane & 16) != 0;
        float val[24];
        #pragma unroll
        for (int c = 0; c < 3; c++) {
            float kA, kB;
            #define FOLD(slotA, slotB, idx) \
                kA = (slotA); kB = (slotB); \
                { float keep = hi ? kB : kA; float send = hi ? kA : kB; \
                  val[idx] = keep + __shfl_xor_sync(0xFFFFFFFFu, send, 16); }
            FOLD(M1[0][c], M1[2][c], 0 + c);
            FOLD(Q2[0][c], Q2[2][c], 3 + c);
            FOLD(PG[0][c], PG[2][c], 6 + c);
            FOLD(M1[1][c], M1[3][c], 9 + c);
            FOLD(Q2[1][c], Q2[3][c], 12 + c);
            FOLD(PG[1][c], PG[3][c], 15 + c);
            FOLD(M2[c],    M2[c],    18 + c);   // single copy -> both halves get total
            FOLD(G2[c],    G2[c],    21 + c);
            #undef FOLD
        }
        #pragma unroll
        for (int off = 8; off; off >>= 1) {
            #pragma unroll
            for (int i = 0; i < 24; i++)
                val[i] += __shfl_xor_sync(0xFFFFFFFFu, val[i], off);
        }

        const float C1 = 1e-4f;   // 0.01^2
        const float C2 = 9e-4f;   // 0.03^2
        float ssim_lo = 0.f, ssim_hi_v = 0.f;
        #pragma unroll
        for (int c = 0; c < 3; c++) {
            float mu2  = val[18 + c];
            float mu2sq = mu2 * mu2;
            float s2   = val[21 + c] - mu2sq;
            {   // view lo
                float mu1 = val[0 + c];
                float mu1sq = mu1 * mu1;
                float mu12  = mu1 * mu2;
                float s1  = val[3 + c] - mu1sq;
                float s12 = val[6 + c] - mu12;
                float num = (2.0f * mu12 + C1) * (2.0f * s12 + C2);
                float den = (mu1sq + mu2sq + C1) * (s1 + s2 + C2);
                ssim_lo += __fdividef(num, den);
            }
            {   // view hi
                float mu1 = val[9 + c];
                float mu1sq = mu1 * mu1;
                float mu12  = mu1 * mu2;
                float s1  = val[12 + c] - mu1sq;
                float s12 = val[15 + c] - mu12;
                float num = (2.0f * mu12 + C1) * (2.0f * s12 + C2);
                float den = (mu1sq + mu2sq + C1) * (s1 + s2 + C2);
                ssim_hi_v += __fdividef(num, den);
            }
        }

        // Writers: lanes 0,1 (views 0,1) and 16,17 (views 2,3).
        if ((lane & 14) == 0) {
            const int q = t * 4 + wid;          // global (n,p) row
            const int n = q >> 4;
            const int p = q & 15;
            int sel  = lane & 1;
            int view = ((lane >> 4) << 1) | sel;
            float res = (sel ? ssim_hi_v : ssim_lo) * (1.0f / 3.0f);
            out[(view * NN + n) * NP + p] = res;
        }
    }
    #undef STAGE
}

extern "C" void kernel_launch(void* const* d_in, const int* in_sizes, int n_in,
                              void* d_out, int out_size)
{
    const float* pred = (const float*)d_in[0];   // img_pred [4,2048,16,121,3]
    const float* gt   = (const float*)d_in[1];   // img_gt   [2048,16,121,3]
    float* out = (float*)d_out;                  // [4,2048,16]

    ssim_kernel<<<GRID, 128>>>(pred, gt, out);   // 888 = 148 SMs x 6 blocks
}

// round 12
// speedup vs baseline: 1.1581x; 1.1581x over previous
#include <cuda_runtime.h>
#include <cstdint>

// SSIM over 11x11 patches — cp.async staging, register-cached gt, f32x2 math,
// staged per-view waits.
// img_pred: [4, 2048, 16, 121, 3] f32   (~190 MB)
// img_gt:   [2048, 16, 121, 3] f32      (~47.6 MB)
// out:      [4, 2048, 16] f32
//
// R11 (persistent ring) regressed — revert to R10 and add the one missing
// overlap: per-view wait groups. gt phase after wait_group 4 (views in
// flight), then view v after wait_group 3-v, so view v+1..3 loads remain
// outstanding during view v compute. gt cached in registers (bcp/bcs) and
// weights in wkp from R10 make the v-outer order free (no smem re-reads).

#define NN       2048
#define NP       16
#define ROW      363                       // 121 patches * 3 channels
#define VSTRIDE  ((size_t)NN * NP * ROW)   // floats per view
#define RPB      4                         // rows per block
#define CHUNK    (RPB * ROW)               // 1452 floats
#define CHUNK4   (CHUNK / 4)               // 363 float4
#define PADF     32                        // zeroed pad floats per array

using ull = unsigned long long;

__device__ __forceinline__ void cp16(uint32_t dst, const void* src) {
    asm volatile("cp.async.cg.shared.global [%0], [%1], 16;" :: "r"(dst), "l"(src));
}
__device__ __forceinline__ ull pk2(float lo, float hi) {
    ull r; asm("mov.b64 %0, {%1, %2};" : "=l"(r) : "f"(lo), "f"(hi)); return r;
}
__device__ __forceinline__ void up2(ull v, float& lo, float& hi) {
    asm("mov.b64 {%0, %1}, %2;" : "=f"(lo), "=f"(hi) : "l"(v));
}
__device__ __forceinline__ ull fma2_(ull a, ull b, ull c) {
    ull d; asm("fma.rn.f32x2 %0, %1, %2, %3;" : "=l"(d) : "l"(a), "l"(b), "l"(c)); return d;
}
__device__ __forceinline__ ull mul2_(ull a, ull b) {
    ull d; asm("mul.rn.f32x2 %0, %1, %2;" : "=l"(d) : "l"(a), "l"(b)); return d;
}
__device__ __forceinline__ ull add2_(ull a, ull b) {
    ull d; asm("add.rn.f32x2 %0, %1, %2;" : "=l"(d) : "l"(a), "l"(b)); return d;
}

__global__ __launch_bounds__(128) void ssim_kernel(
    const float* __restrict__ pred,
    const float* __restrict__ gt,
    float* __restrict__ out)
{
    __shared__ float sG[CHUNK + PADF];       // gt, 4 rows (+pad)
    __shared__ float sP[4][CHUNK + PADF];    // pred, 4 views x 4 rows (+pad)
    __shared__ float sg6[6];                 // 1-D gaussian, |d| = 0..5
    __shared__ float sW[128];                // per-patch weights, 0 for p>=121

    const int tid = threadIdx.x;
    const int q0  = blockIdx.x * RPB;        // first (n,p) row of this block

    // ---- stage: 5 streams, each its own commit group ----
    {
        const uint32_t dG = (uint32_t)__cvta_generic_to_shared(sG);
        const float4* __restrict__ srcG = (const float4*)(gt + (size_t)q0 * ROW);
        for (int i = tid; i < CHUNK4; i += 128)
            cp16(dG + i * 16, srcG + i);
        asm volatile("cp.async.commit_group;");          // group: gt

        #pragma unroll
        for (int v = 0; v < 4; v++) {
            const uint32_t dP = (uint32_t)__cvta_generic_to_shared(sP[v]);
            const float4* __restrict__ srcP =
                (const float4*)(pred + v * VSTRIDE + (size_t)q0 * ROW);
            for (int i = tid; i < CHUNK4; i += 128)
                cp16(dP + i * 16, srcP + i);
            asm volatile("cp.async.commit_group;");      // group: view v
        }
    }

    // ---- while loads fly: zero pads, build weight table ----
    if (tid < PADF) {
        sG[CHUNK + tid] = 0.f;
        sP[0][CHUNK + tid] = 0.f;
        sP[1][CHUNK + tid] = 0.f;
        sP[2][CHUNK + tid] = 0.f;
        sP[3][CHUNK + tid] = 0.f;
    }
    if (tid < 6) {
        float d = (float)tid;
        sg6[tid] = expf(-d * d * (1.0f / 4.5f));   // sigma = 1.5
    }
    __syncthreads();
    {
        float S = sg6[0] + 2.0f * (sg6[1] + sg6[2] + sg6[3] + sg6[4] + sg6[5]);
        float invS2 = 1.0f / (S * S);
        if (tid < 121) {
            int py = tid / 11, px = tid % 11;
            int dy = py - 5; if (dy < 0) dy = -dy;
            int dx = px - 5; if (dx < 0) dx = -dx;
            sW[tid] = sg6[dy] * sg6[dx] * invS2;
        } else if (tid < 128) {
            sW[tid] = 0.f;                          // tail patches contribute 0
        }
    }

    const int wid  = tid >> 5;
    const int lane = tid & 31;
    const int wbase = wid * ROW;

    // Accumulators: channels (0,1) packed, channel 2 scalar.
    ull  m1p[4], q2p[4], pgp[4];
    float m1s[4], q2s[4], pgs[4];
    ull  m2p = 0, g2p = 0;
    float m2s = 0.f, g2s = 0.f;
    #pragma unroll
    for (int v = 0; v < 4; v++) {
        m1p[v] = 0; q2p[v] = 0; pgp[v] = 0;
        m1s[v] = 0.f; q2s[v] = 0.f; pgs[v] = 0.f;
    }

    float wk[4];  ull wkp[4];
    ull   bcp[4];    // cached gt (ch0,ch1) per k
    float bcs[4];    // cached gt ch2 per k

    // ---- gt phase: wait only the gt group (views still in flight) ----
    asm volatile("cp.async.wait_group 4;");
    __syncthreads();          // publishes gt buffer, pads, sW
    #pragma unroll
    for (int k = 0; k < 4; k++) {
        wk[k]  = sW[k * 32 + lane];
        wkp[k] = pk2(wk[k], wk[k]);
    }

    #pragma unroll
    for (int k = 0; k < 4; k++) {
        const int base = wbase + 3 * (k * 32 + lane);
        const float b0 = sG[base + 0];
        const float b1 = sG[base + 1];
        const float b2 = sG[base + 2];
        const ull bp = pk2(b0, b1);
        bcp[k] = bp;  bcs[k] = b2;
        const ull wbp = mul2_(wkp[k], bp);
        m2p = add2_(m2p, wbp);
        g2p = fma2_(wbp, bp, g2p);
        const float wb2 = wk[k] * b2;
        m2s += wb2;
        g2s = fmaf(wb2, b2, g2s);
    }

    // ---- view phases: wait each view's group just before consuming it ----
    #pragma unroll
    for (int v = 0; v < 4; v++) {
        if (v == 0) asm volatile("cp.async.wait_group 3;");
        if (v == 1) asm volatile("cp.async.wait_group 2;");
        if (v == 2) asm volatile("cp.async.wait_group 1;");
        if (v == 3) asm volatile("cp.async.wait_group 0;");
        __syncthreads();      // view v buffer visible block-wide

        #pragma unroll
        for (int k = 0; k < 4; k++) {
            const int base = wbase + 3 * (k * 32 + lane);
            const float a0 = sP[v][base + 0];
            const float a1 = sP[v][base + 1];
            const float a2 = sP[v][base + 2];
            const ull ap = pk2(a0, a1);
            const ull wa = mul2_(wkp[k], ap);
            m1p[v] = add2_(m1p[v], wa);
            q2p[v] = fma2_(wa, ap, q2p[v]);
            pgp[v] = fma2_(wa, bcp[k], pgp[v]);
            const float wa2 = wk[k] * a2;
            m1s[v] += wa2;
            q2s[v] = fmaf(wa2, a2, q2s[v]);
            pgs[v] = fmaf(wa2, bcs[k], pgs[v]);
        }
    }

    // Unpack to per-channel floats.
    float M1[4][3], Q2[4][3], PG[4][3], M2[3], G2[3];
    #pragma unroll
    for (int v = 0; v < 4; v++) {
        up2(m1p[v], M1[v][0], M1[v][1]);  M1[v][2] = m1s[v];
        up2(q2p[v], Q2[v][0], Q2[v][1]);  Q2[v][2] = q2s[v];
        up2(pgp[v], PG[v][0], PG[v][1]);  PG[v][2] = pgs[v];
    }
    up2(m2p, M2[0], M2[1]);  M2[2] = m2s;
    up2(g2p, G2[0], G2[1]);  G2[2] = g2s;

    // Fold across lane-bit-16: lanes 0-15 -> views 0,1; 16-31 -> views 2,3.
    const bool hi = (lane & 16) != 0;
    float val[24];
    #pragma unroll
    for (int c = 0; c < 3; c++) {
        float kA, kB;
        #define FOLD(slotA, slotB, idx) \
            kA = (slotA); kB = (slotB); \
            { float keep = hi ? kB : kA; float send = hi ? kA : kB; \
              val[idx] = keep + __shfl_xor_sync(0xFFFFFFFFu, send, 16); }
        FOLD(M1[0][c], M1[2][c], 0 + c);
        FOLD(Q2[0][c], Q2[2][c], 3 + c);
        FOLD(PG[0][c], PG[2][c], 6 + c);
        FOLD(M1[1][c], M1[3][c], 9 + c);
        FOLD(Q2[1][c], Q2[3][c], 12 + c);
        FOLD(PG[1][c], PG[3][c], 15 + c);
        FOLD(M2[c],    M2[c],    18 + c);   // single copy -> both halves get total
        FOLD(G2[c],    G2[c],    21 + c);
        #undef FOLD
    }

    // Butterfly within each 16-lane half.
    #pragma unroll
    for (int off = 8; off; off >>= 1) {
        #pragma unroll
        for (int i = 0; i < 24; i++)
            val[i] += __shfl_xor_sync(0xFFFFFFFFu, val[i], off);
    }

    // Epilogue: each lane computes SSIM for its half's two views.
    const float C1 = 1e-4f;   // 0.01^2
    const float C2 = 9e-4f;   // 0.03^2
    float ssim_lo = 0.f, ssim_hi_v = 0.f;
    #pragma unroll
    for (int c = 0; c < 3; c++) {
        float mu2  = val[18 + c];
        float mu2sq = mu2 * mu2;
        float s2   = val[21 + c] - mu2sq;
        {   // view lo
            float mu1 = val[0 + c];
            float mu1sq = mu1 * mu1;
            float mu12  = mu1 * mu2;
            float s1  = val[3 + c] - mu1sq;
            float s12 = val[6 + c] - mu12;
            float num = (2.0f * mu12 + C1) * (2.0f * s12 + C2);
            float den = (mu1sq + mu2sq + C1) * (s1 + s2 + C2);
            ssim_lo += __fdividef(num, den);
        }
        {   // view hi
            float mu1 = val[9 + c];
            float mu1sq = mu1 * mu1;
            float mu12  = mu1 * mu2;
            float s1  = val[12 + c] - mu1sq;
            float s12 = val[15 + c] - mu12;
            float num = (2.0f * mu12 + C1) * (2.0f * s12 + C2);
            float den = (mu1sq + mu2sq + C1) * (s1 + s2 + C2);
            ssim_hi_v += __fdividef(num, den);
        }
    }

    // Writers: lanes 0,1 (views 0,1) and 16,17 (views 2,3).
    if ((lane & 14) == 0) {
        const int q = q0 + wid;
        const int n = q >> 4;
        const int p = q & 15;
        int sel  = lane & 1;
        int view = ((lane >> 4) << 1) | sel;
        float res = (sel ? ssim_hi_v : ssim_lo) * (1.0f / 3.0f);
        out[(view * NN + n) * NP + p] = res;
    }
}

extern "C" void kernel_launch(void* const* d_in, const int* in_sizes, int n_in,
                              void* d_out, int out_size)
{
    const float* pred = (const float*)d_in[0];   // img_pred [4,2048,16,121,3]
    const float* gt   = (const float*)d_in[1];   // img_gt   [2048,16,121,3]
    float* out = (float*)d_out;                  // [4,2048,16]

    const int blocks = (NN * NP) / RPB;          // 8192 blocks, 4 rows each
    ssim_kernel<<<blocks, 128>>>(pred, gt, out);
}

// round 13
// speedup vs baseline: 1.1910x; 1.0284x over previous
#include <cuda_runtime.h>
#include <cstdint>

// SSIM over 11x11 patches — bulk-TMA (cp.async.bulk) staging + mbarriers,
// register-cached gt, f32x2 math, warp-autonomous per-stream waits.
// img_pred: [4, 2048, 16, 121, 3] f32   (~190 MB)
// img_gt:   [2048, 16, 121, 3] f32      (~47.6 MB)
// out:      [4, 2048, 16] f32
//
// R12 -> R13: the 5 streams (gt, view0..3; each 5808 B = 363 x 16 B) are
// loaded by FIVE single cp.async.bulk ops (tid 0) completing on per-stream
// mbarriers, instead of ~15 LDGSTS + address ALU per thread. Consumers use
// mbarrier.try_wait.parity.acquire per stream — no block-wide barriers in
// the consume path (acquire publishes the TMA writes), warps self-pace.
// One __syncthreads total (publishes mbarrier init + weight table + pads).
// Compute unchanged from R12: register gt cache, packed f32x2 stats,
// bit-16 fold + 16-lane butterfly, 4 outputs per warp.

#define NN       2048
#define NP       16
#define ROW      363                       // 121 patches * 3 channels
#define VSTRIDE  ((size_t)NN * NP * ROW)   // floats per view
#define RPB      4                         // rows per block
#define CHUNK    (RPB * ROW)               // 1452 floats
#define CHUNKB   (CHUNK * 4)               // 5808 bytes (16B multiple)
#define PADF     32                        // zeroed pad floats per array

using ull = unsigned long long;

__device__ __forceinline__ uint32_t s2u(const void* p) {
    return (uint32_t)__cvta_generic_to_shared(p);
}
__device__ __forceinline__ void mbar_init(uint32_t a, uint32_t cnt) {
    asm volatile("mbarrier.init.shared.b64 [%0], %1;" :: "r"(a), "r"(cnt) : "memory");
}
__device__ __forceinline__ void mbar_expect_tx(uint32_t a, uint32_t bytes) {
    asm volatile("mbarrier.arrive.expect_tx.shared.b64 _, [%0], %1;"
                 :: "r"(a), "r"(bytes) : "memory");
}
__device__ __forceinline__ void bulk_g2s(uint32_t dst, const void* src,
                                         uint32_t bytes, uint32_t mbar) {
    asm volatile(
        "cp.async.bulk.shared::cta.global.mbarrier::complete_tx::bytes "
        "[%0], [%1], %2, [%3];"
        :: "r"(dst), "l"(src), "r"(bytes), "r"(mbar) : "memory");
}
__device__ __forceinline__ void mbar_wait0(uint32_t a) {
    uint32_t done = 0;
    while (!done) {
        asm volatile(
            "{\n\t.reg .pred p;\n\t"
            "mbarrier.try_wait.parity.acquire.cta.shared::cta.b64 p, [%1], %2, 0x989680;\n\t"
            "selp.b32 %0, 1, 0, p;\n\t}"
            : "=r"(done) : "r"(a), "r"(0u) : "memory");
    }
}
__device__ __forceinline__ ull pk2(float lo, float hi) {
    ull r; asm("mov.b64 %0, {%1, %2};" : "=l"(r) : "f"(lo), "f"(hi)); return r;
}
__device__ __forceinline__ void up2(ull v, float& lo, float& hi) {
    asm("mov.b64 {%0, %1}, %2;" : "=f"(lo), "=f"(hi) : "l"(v));
}
__device__ __forceinline__ ull fma2_(ull a, ull b, ull c) {
    ull d; asm("fma.rn.f32x2 %0, %1, %2, %3;" : "=l"(d) : "l"(a), "l"(b), "l"(c)); return d;
}
__device__ __forceinline__ ull mul2_(ull a, ull b) {
    ull d; asm("mul.rn.f32x2 %0, %1, %2;" : "=l"(d) : "l"(a), "l"(b)); return d;
}
__device__ __forceinline__ ull add2_(ull a, ull b) {
    ull d; asm("add.rn.f32x2 %0, %1, %2;" : "=l"(d) : "l"(a), "l"(b)); return d;
}

__global__ __launch_bounds__(128) void ssim_kernel(
    const float* __restrict__ pred,
    const float* __restrict__ gt,
    float* __restrict__ out)
{
    __shared__ __align__(16) float sG[CHUNK + PADF];     // gt, 4 rows (+pad)
    __shared__ __align__(16) float sP[4][CHUNK + PADF];  // pred, 4 views (+pad)
    __shared__ float sW[128];                            // per-patch weights
    __shared__ __align__(8) ull mbars[5];                // gt, view0..3

    const int tid = threadIdx.x;
    const int q0  = blockIdx.x * RPB;        // first (n,p) row of this block

    // ---- tid 0: init mbarriers, fence, issue the 5 bulk copies ----
    if (tid == 0) {
        #pragma unroll
        for (int s = 0; s < 5; s++) mbar_init(s2u(&mbars[s]), 1);
        asm volatile("fence.proxy.async.shared::cta;" ::: "memory");

        mbar_expect_tx(s2u(&mbars[0]), CHUNKB);
        bulk_g2s(s2u(sG), gt + (size_t)q0 * ROW, CHUNKB, s2u(&mbars[0]));
        #pragma unroll
        for (int v = 0; v < 4; v++) {
            mbar_expect_tx(s2u(&mbars[v + 1]), CHUNKB);
            bulk_g2s(s2u(sP[v]), pred + v * VSTRIDE + (size_t)q0 * ROW,
                     CHUNKB, s2u(&mbars[v + 1]));
        }
    }

    // ---- concurrently: zero pads, build weight table ----
    if (tid < PADF) {
        sG[CHUNK + tid] = 0.f;
        sP[0][CHUNK + tid] = 0.f;
        sP[1][CHUNK + tid] = 0.f;
        sP[2][CHUNK + tid] = 0.f;
        sP[3][CHUNK + tid] = 0.f;
    }
    {
        // 1/S^2 from the 1-D gaussian sum (uniform across threads, CSE'd).
        const float inv2s2 = 1.0f / 4.5f;   // 1/(2*sigma^2), sigma=1.5
        float S = 1.0f + 2.0f * (expf(-1.0f * inv2s2) + expf(-4.0f * inv2s2) +
                                 expf(-9.0f * inv2s2) + expf(-16.0f * inv2s2) +
                                 expf(-25.0f * inv2s2));
        float invS2 = 1.0f / (S * S);
        if (tid < 121) {
            int py = tid / 11, px = tid % 11;
            float dy = (float)(py - 5), dx = (float)(px - 5);
            sW[tid] = expf(-(dy * dy + dx * dx) * inv2s2) * invS2;
        } else {
            sW[tid] = 0.f;                  // tail patches contribute 0
        }
    }
    __syncthreads();   // publishes mbarrier init, sW, pads — the ONLY barrier

    const int wid  = tid >> 5;
    const int lane = tid & 31;
    const int wbase = wid * ROW;

    float wk[4];  ull wkp[4];
    #pragma unroll
    for (int k = 0; k < 4; k++) {
        wk[k]  = sW[k * 32 + lane];
        wkp[k] = pk2(wk[k], wk[k]);
    }

    // Accumulators: channels (0,1) packed, channel 2 scalar.
    ull  m1p[4], q2p[4], pgp[4];
    float m1s[4], q2s[4], pgs[4];
    ull  m2p = 0, g2p = 0;
    float m2s = 0.f, g2s = 0.f;
    #pragma unroll
    for (int v = 0; v < 4; v++) {
        m1p[v] = 0; q2p[v] = 0; pgp[v] = 0;
        m1s[v] = 0.f; q2s[v] = 0.f; pgs[v] = 0.f;
    }
    ull   bcp[4];    // cached gt (ch0,ch1) per k
    float bcs[4];    // cached gt ch2 per k

    // ---- gt phase: wait gt mbarrier only (views still in flight) ----
    mbar_wait0(s2u(&mbars[0]));
    #pragma unroll
    for (int k = 0; k < 4; k++) {
        const int base = wbase + 3 * (k * 32 + lane);
        const float b0 = sG[base + 0];
        const float b1 = sG[base + 1];
        const float b2 = sG[base + 2];
        const ull bp = pk2(b0, b1);
        bcp[k] = bp;  bcs[k] = b2;
        const ull wbp = mul2_(wkp[k], bp);
        m2p = add2_(m2p, wbp);
        g2p = fma2_(wbp, bp, g2p);
        const float wb2 = wk[k] * b2;
        m2s += wb2;
        g2s = fmaf(wb2, b2, g2s);
    }

    // ---- view phases: warp-autonomous waits, no block barriers ----
    #pragma unroll
    for (int v = 0; v < 4; v++) {
        mbar_wait0(s2u(&mbars[v + 1]));
        #pragma unroll
        for (int k = 0; k < 4; k++) {
            const int base = wbase + 3 * (k * 32 + lane);
            const float a0 = sP[v][base + 0];
            const float a1 = sP[v][base + 1];
            const float a2 = sP[v][base + 2];
            const ull ap = pk2(a0, a1);
            const ull wa = mul2_(wkp[k], ap);
            m1p[v] = add2_(m1p[v], wa);
            q2p[v] = fma2_(wa, ap, q2p[v]);
            pgp[v] = fma2_(wa, bcp[k], pgp[v]);
            const float wa2 = wk[k] * a2;
            m1s[v] += wa2;
            q2s[v] = fmaf(wa2, a2, q2s[v]);
            pgs[v] = fmaf(wa2, bcs[k], pgs[v]);
        }
    }

    // Unpack to per-channel floats.
    float M1[4][3], Q2[4][3], PG[4][3], M2[3], G2[3];
    #pragma unroll
    for (int v = 0; v < 4; v++) {
        up2(m1p[v], M1[v][0], M1[v][1]);  M1[v][2] = m1s[v];
        up2(q2p[v], Q2[v][0], Q2[v][1]);  Q2[v][2] = q2s[v];
        up2(pgp[v], PG[v][0], PG[v][1]);  PG[v][2] = pgs[v];
    }
    up2(m2p, M2[0], M2[1]);  M2[2] = m2s;
    up2(g2p, G2[0], G2[1]);  G2[2] = g2s;

    // Fold across lane-bit-16: lanes 0-15 -> views 0,1; 16-31 -> views 2,3.
    const bool hi = (lane & 16) != 0;
    float val[24];
    #pragma unroll
    for (int c = 0; c < 3; c++) {
        float kA, kB;
        #define FOLD(slotA, slotB, idx) \
            kA = (slotA); kB = (slotB); \
            { float keep = hi ? kB : kA; float send = hi ? kA : kB; \
              val[idx] = keep + __shfl_xor_sync(0xFFFFFFFFu, send, 16); }
        FOLD(M1[0][c], M1[2][c], 0 + c);
        FOLD(Q2[0][c], Q2[2][c], 3 + c);
        FOLD(PG[0][c], PG[2][c], 6 + c);
        FOLD(M1[1][c], M1[3][c], 9 + c);
        FOLD(Q2[1][c], Q2[3][c], 12 + c);
        FOLD(PG[1][c], PG[3][c], 15 + c);
        FOLD(M2[c],    M2[c],    18 + c);   // single copy -> both halves get total
        FOLD(G2[c],    G2[c],    21 + c);
        #undef FOLD
    }

    // Butterfly within each 16-lane half.
    #pragma unroll
    for (int off = 8; off; off >>= 1) {
        #pragma unroll
        for (int i = 0; i < 24; i++)
            val[i] += __shfl_xor_sync(0xFFFFFFFFu, val[i], off);
    }

    // Epilogue: each lane computes SSIM for its half's two views.
    const float C1 = 1e-4f;   // 0.01^2
    const float C2 = 9e-4f;   // 0.03^2
    float ssim_lo = 0.f, ssim_hi_v = 0.f;
    #pragma unroll
    for (int c = 0; c < 3; c++) {
        float mu2  = val[18 + c];
        float mu2sq = mu2 * mu2;
        float s2   = val[21 + c] - mu2sq;
        {   // view lo
            float mu1 = val[0 + c];
            float mu1sq = mu1 * mu1;
            float mu12  = mu1 * mu2;
            float s1  = val[3 + c] - mu1sq;
            float s12 = val[6 + c] - mu12;
            float num = (2.0f * mu12 + C1) * (2.0f * s12 + C2);
            float den = (mu1sq + mu2sq + C1) * (s1 + s2 + C2);
            ssim_lo += __fdividef(num, den);
        }
        {   // view hi
            float mu1 = val[9 + c];
            float mu1sq = mu1 * mu1;
            float mu12  = mu1 * mu2;
            float s1  = val[12 + c] - mu1sq;
            float s12 = val[15 + c] - mu12;
            float num = (2.0f * mu12 + C1) * (2.0f * s12 + C2);
            float den = (mu1sq + mu2sq + C1) * (s1 + s2 + C2);
            ssim_hi_v += __fdividef(num, den);
        }
    }

    // Writers: lanes 0,1 (views 0,1) and 16,17 (views 2,3).
    if ((lane & 14) == 0) {
        const int q = q0 + wid;
        const int n = q >> 4;
        const int p = q & 15;
        int sel  = lane & 1;
        int view = ((lane >> 4) << 1) | sel;
        float res = (sel ? ssim_hi_v : ssim_lo) * (1.0f / 3.0f);
        out[(view * NN + n) * NP + p] = res;
    }
}

extern "C" void kernel_launch(void* const* d_in, const int* in_sizes, int n_in,
                              void* d_out, int out_size)
{
    const float* pred = (const float*)d_in[0];   // img_pred [4,2048,16,121,3]
    const float* gt   = (const float*)d_in[1];   // img_gt   [2048,16,121,3]
    float* out = (float*)d_out;                  // [4,2048,16]

    const int blocks = (NN * NP) / RPB;          // 8192 blocks, 4 rows each
    ssim_kernel<<<blocks, 128>>>(pred, gt, out);
}